// round 1
// baseline (speedup 1.0000x reference)
#include <cuda_runtime.h>

#define EDIM   1024
#define BATCH  2
#define SEQ    2048
#define NHEADS 16
#define HDIM   64
#define WIN    128
#define MROWS  (BATCH*SEQ)

// Scratch (allocation-free rule: __device__ globals)
__device__ float g_Q[MROWS*EDIM];
__device__ float g_K[MROWS*EDIM];
__device__ float g_V[MROWS*EDIM];
__device__ float g_A[MROWS*EDIM];

// ---------------------------------------------------------------------------
// GEMM: C[M,N] = A[M,K] @ W[N,K]^T + bias[N]   (torch Linear, both K-major)
// 128x128 tile, BK=8, 256 threads, 8x8 per-thread micro-tile.
// ---------------------------------------------------------------------------
#define BM 128
#define BN 128
#define BKK 8
#define TM 8
#define TN 8
#define ASTR (BM+4)   // 132, multiple of 4 for float4 smem loads

__device__ __forceinline__ void gemm_body(const float* __restrict__ A,
                                          const float* __restrict__ W,
                                          const float* __restrict__ bias,
                                          float* __restrict__ C)
{
    __shared__ float sA[BKK][ASTR];
    __shared__ float sW[BKK][ASTR];
    const int K = EDIM, N = EDIM;

    int tid = threadIdx.x;
    int tx = tid & 15, ty = tid >> 4;
    int row0 = blockIdx.y * BM;
    int col0 = blockIdx.x * BN;

    float acc[TM][TN];
#pragma unroll
    for (int i = 0; i < TM; i++)
#pragma unroll
        for (int j = 0; j < TN; j++) acc[i][j] = 0.f;

    int lr = tid >> 1;          // 0..127 (row within tile)
    int lk = (tid & 1) << 2;    // 0 or 4 (k offset)
    const float* Ap = A + (size_t)(row0 + lr) * K + lk;
    const float* Wp = W + (size_t)(col0 + lr) * K + lk;

    for (int k0 = 0; k0 < K; k0 += BKK) {
        float4 av = *(const float4*)(Ap + k0);
        float4 wv = *(const float4*)(Wp + k0);
        sA[lk+0][lr]=av.x; sA[lk+1][lr]=av.y; sA[lk+2][lr]=av.z; sA[lk+3][lr]=av.w;
        sW[lk+0][lr]=wv.x; sW[lk+1][lr]=wv.y; sW[lk+2][lr]=wv.z; sW[lk+3][lr]=wv.w;
        __syncthreads();
#pragma unroll
        for (int kk = 0; kk < BKK; kk++) {
            float4 a0 = *(const float4*)&sA[kk][ty*TM];
            float4 a1 = *(const float4*)&sA[kk][ty*TM+4];
            float4 b0 = *(const float4*)&sW[kk][tx*TN];
            float4 b1 = *(const float4*)&sW[kk][tx*TN+4];
            float a[TM] = {a0.x,a0.y,a0.z,a0.w,a1.x,a1.y,a1.z,a1.w};
            float b[TN] = {b0.x,b0.y,b0.z,b0.w,b1.x,b1.y,b1.z,b1.w};
#pragma unroll
            for (int i = 0; i < TM; i++)
#pragma unroll
                for (int j = 0; j < TN; j++)
                    acc[i][j] = fmaf(a[i], b[j], acc[i][j]);
        }
        __syncthreads();
    }

#pragma unroll
    for (int i = 0; i < TM; i++) {
        int r = row0 + ty*TM + i;
#pragma unroll
        for (int j = 0; j < TN; j += 4) {
            int c = col0 + tx*TN + j;
            float4 o;
            o.x = acc[i][j+0] + bias[c+0];
            o.y = acc[i][j+1] + bias[c+1];
            o.z = acc[i][j+2] + bias[c+2];
            o.w = acc[i][j+3] + bias[c+3];
            *(float4*)&C[(size_t)r*N + c] = o;
        }
    }
}

__global__ void __launch_bounds__(256)
proj_qkv_kernel(const float* __restrict__ q, const float* __restrict__ k,
                const float* __restrict__ v,
                const float* __restrict__ Wq, const float* __restrict__ bq,
                const float* __restrict__ Wk, const float* __restrict__ bk,
                const float* __restrict__ Wv, const float* __restrict__ bv)
{
    const float *A, *W, *b; float* C;
    if (blockIdx.z == 0)      { A = q; W = Wq; b = bq; C = g_Q; }
    else if (blockIdx.z == 1) { A = k; W = Wk; b = bk; C = g_K; }
    else                      { A = v; W = Wv; b = bv; C = g_V; }
    gemm_body(A, W, b, C);
}

__global__ void __launch_bounds__(256)
out_proj_kernel(const float* __restrict__ Wo, const float* __restrict__ bo,
                float* __restrict__ out)
{
    gemm_body(g_A, Wo, bo, out);
}

// ---------------------------------------------------------------------------
// Sliding-window attention, flash-style. One CTA per (128-query block, head, b).
// Band |i-j|<=128 => only key blocks {qb-1, qb, qb+1} contribute.
// ---------------------------------------------------------------------------
#define BQ   128
#define BKC  128
#define QSTR 132   // sQt/sKt row stride (float4-aligned, odd-bank-ish)
#define VSTR 68    // sV row stride (float4-aligned)
#define PSTR 132

#define SQT_SZ (HDIM*QSTR)      // 8448
#define SKT_SZ (HDIM*QSTR)      // 8448
#define SV_SZ  (BKC*VSTR)       // 8704
#define SP_SZ  (BQ*PSTR)        // 16896
#define ATTN_SMEM_FLOATS (SQT_SZ + SKT_SZ + SV_SZ + SP_SZ)
#define ATTN_SMEM_BYTES  (ATTN_SMEM_FLOATS * 4)   // 169984

__global__ void __launch_bounds__(256)
attn_kernel()
{
    extern __shared__ float smem[];
    float* sQt = smem;                  // [64][132]  (d-major, transposed)
    float* sKt = sQt + SQT_SZ;          // [64][132]
    float* sV  = sKt + SKT_SZ;          // [128][68]
    float* sP  = sV  + SV_SZ;           // [128][132]

    const int tid = threadIdx.x;
    const int tx  = tid & 15;           // score cols / output dims
    const int ty  = tid >> 4;           // score rows
    const int qb  = blockIdx.x;
    const int h   = blockIdx.y;
    const int b   = blockIdx.z;
    const int q0  = qb * BQ;

    const float* Qb = g_Q + (size_t)b*SEQ*EDIM + (size_t)h*HDIM;
    const float* Kb = g_K + (size_t)b*SEQ*EDIM + (size_t)h*HDIM;
    const float* Vb = g_V + (size_t)b*SEQ*EDIM + (size_t)h*HDIM;
    float*       Ob = g_A + (size_t)b*SEQ*EDIM + (size_t)h*HDIM;

    // Load Q tile transposed: sQt[d][i]
#pragma unroll
    for (int it = 0; it < 8; it++) {
        int idx = tid + it*256;             // float4 index, 2048 total
        int r  = idx >> 4;                  // 0..127
        int d4 = (idx & 15) << 2;           // 0..60
        float4 qv = *(const float4*)(Qb + (size_t)(q0 + r)*EDIM + d4);
        sQt[(d4+0)*QSTR + r] = qv.x;
        sQt[(d4+1)*QSTR + r] = qv.y;
        sQt[(d4+2)*QSTR + r] = qv.z;
        sQt[(d4+3)*QSTR + r] = qv.w;
    }

    const int i0 = ty * 8;
    const int d0 = tx * 4;
    float m_i[8], l_i[8], o[8][4];
#pragma unroll
    for (int i = 0; i < 8; i++) {
        m_i[i] = -1e30f; l_i[i] = 0.f;
        o[i][0]=o[i][1]=o[i][2]=o[i][3]=0.f;
    }

    const int nkb = SEQ / BKC;
    for (int kb = qb - 1; kb <= qb + 1; kb++) {
        if (kb < 0 || kb >= nkb) continue;
        const int j0 = kb * BKC;

        __syncthreads();  // prior PV / Q-load done before overwriting K,V,P
        // Load K transposed + V
#pragma unroll
        for (int it = 0; it < 8; it++) {
            int idx = tid + it*256;
            int r  = idx >> 4;
            int d4 = (idx & 15) << 2;
            float4 kv = *(const float4*)(Kb + (size_t)(j0 + r)*EDIM + d4);
            sKt[(d4+0)*QSTR + r] = kv.x;
            sKt[(d4+1)*QSTR + r] = kv.y;
            sKt[(d4+2)*QSTR + r] = kv.z;
            sKt[(d4+3)*QSTR + r] = kv.w;
            float4 vv = *(const float4*)(Vb + (size_t)(j0 + r)*EDIM + d4);
            *(float4*)&sV[r*VSTR + d4] = vv;
        }
        __syncthreads();

        // Scores: S = Q @ K^T  (8x8 per thread over 128x128)
        float s[8][8];
#pragma unroll
        for (int i = 0; i < 8; i++)
#pragma unroll
            for (int j = 0; j < 8; j++) s[i][j] = 0.f;

#pragma unroll 4
        for (int d = 0; d < HDIM; d++) {
            float4 a0 = *(const float4*)&sQt[d*QSTR + i0];
            float4 a1 = *(const float4*)&sQt[d*QSTR + i0 + 4];
            float4 b0 = *(const float4*)&sKt[d*QSTR + tx*8];
            float4 b1 = *(const float4*)&sKt[d*QSTR + tx*8 + 4];
            float a[8] = {a0.x,a0.y,a0.z,a0.w,a1.x,a1.y,a1.z,a1.w};
            float bb[8] = {b0.x,b0.y,b0.z,b0.w,b1.x,b1.y,b1.z,b1.w};
#pragma unroll
            for (int i = 0; i < 8; i++)
#pragma unroll
                for (int j = 0; j < 8; j++)
                    s[i][j] = fmaf(a[i], bb[j], s[i][j]);
        }

        // Scale + band mask
#pragma unroll
        for (int i = 0; i < 8; i++) {
            int gi = q0 + i0 + i;
#pragma unroll
            for (int j = 0; j < 8; j++) {
                int gj = j0 + tx*8 + j;
                int dd = gi - gj; dd = dd < 0 ? -dd : dd;
                s[i][j] = (dd > WIN) ? -1e30f : s[i][j] * 0.125f;
            }
        }

        // Online softmax (row reduce over 16 tx-lanes via shfl_xor)
#pragma unroll
        for (int i = 0; i < 8; i++) {
            float rm = s[i][0];
#pragma unroll
            for (int j = 1; j < 8; j++) rm = fmaxf(rm, s[i][j]);
#pragma unroll
            for (int off = 8; off >= 1; off >>= 1)
                rm = fmaxf(rm, __shfl_xor_sync(0xffffffffu, rm, off));
            float mnew = fmaxf(m_i[i], rm);
            float corr = __expf(m_i[i] - mnew);
            float rs = 0.f;
#pragma unroll
            for (int j = 0; j < 8; j++) {
                float p = __expf(s[i][j] - mnew);
                s[i][j] = p; rs += p;
            }
#pragma unroll
            for (int off = 8; off >= 1; off >>= 1)
                rs += __shfl_xor_sync(0xffffffffu, rs, off);
            l_i[i] = l_i[i] * corr + rs;
            m_i[i] = mnew;
            o[i][0] *= corr; o[i][1] *= corr; o[i][2] *= corr; o[i][3] *= corr;
        }

        // Write P
#pragma unroll
        for (int i = 0; i < 8; i++) {
            float4 p0 = {s[i][0], s[i][1], s[i][2], s[i][3]};
            float4 p1 = {s[i][4], s[i][5], s[i][6], s[i][7]};
            *(float4*)&sP[(i0+i)*PSTR + tx*8]     = p0;
            *(float4*)&sP[(i0+i)*PSTR + tx*8 + 4] = p1;
        }
        __syncthreads();

        // O += P @ V   (8 rows x 4 dims per thread; sP column reads broadcast)
#pragma unroll 2
        for (int j = 0; j < BKC; j++) {
            float4 vv = *(const float4*)&sV[j*VSTR + d0];
#pragma unroll
            for (int i = 0; i < 8; i++) {
                float p = sP[(i0+i)*PSTR + j];
                o[i][0] = fmaf(p, vv.x, o[i][0]);
                o[i][1] = fmaf(p, vv.y, o[i][1]);
                o[i][2] = fmaf(p, vv.z, o[i][2]);
                o[i][3] = fmaf(p, vv.w, o[i][3]);
            }
        }
    }

    // Normalize + store
#pragma unroll
    for (int i = 0; i < 8; i++) {
        float inv = 1.0f / l_i[i];
        float4 res = {o[i][0]*inv, o[i][1]*inv, o[i][2]*inv, o[i][3]*inv};
        *(float4*)(Ob + (size_t)(q0 + i0 + i)*EDIM + d0) = res;
    }
}

// ---------------------------------------------------------------------------
extern "C" void kernel_launch(void* const* d_in, const int* in_sizes, int n_in,
                              void* d_out, int out_size)
{
    const float* q  = (const float*)d_in[0];
    const float* k  = (const float*)d_in[1];
    const float* v  = (const float*)d_in[2];
    const float* Wq = (const float*)d_in[3];
    const float* bq = (const float*)d_in[4];
    const float* Wk = (const float*)d_in[5];
    const float* bk = (const float*)d_in[6];
    const float* Wv = (const float*)d_in[7];
    const float* bv = (const float*)d_in[8];
    const float* Wo = (const float*)d_in[9];
    const float* bo = (const float*)d_in[10];
    float* out = (float*)d_out;

    cudaFuncSetAttribute(attn_kernel,
                         cudaFuncAttributeMaxDynamicSharedMemorySize,
                         ATTN_SMEM_BYTES);

    dim3 gProj(EDIM/BN, MROWS/BM, 3);
    proj_qkv_kernel<<<gProj, 256>>>(q, k, v, Wq, bq, Wk, bk, Wv, bv);

    dim3 gAttn(SEQ/BQ, NHEADS, BATCH);
    attn_kernel<<<gAttn, 256, ATTN_SMEM_BYTES>>>();

    dim3 gOut(EDIM/BN, MROWS/BM, 1);
    out_proj_kernel<<<gOut, 256>>>(Wo, bo, out);
}

// round 3
// speedup vs baseline: 1.9660x; 1.9660x over previous
#include <cuda_runtime.h>
#include <cuda_bf16.h>
#include <cstdint>

#define EDIM   1024
#define BATCH  2
#define SEQ    2048
#define NHEADS 16
#define HDIM   64
#define WIN    128
#define MROWS  (BATCH*SEQ)

// Scratch (allocation-free rule: __device__ globals)
__device__ float g_Q[MROWS*EDIM];
__device__ float g_K[MROWS*EDIM];
__device__ float g_V[MROWS*EDIM];
__device__ float g_A[MROWS*EDIM];

// ===========================================================================
// bf16 mma.sync GEMM, 3-product compensated split (fp32-class accuracy):
//   C[M,N] = A[M,K] @ W[N,K]^T + bias[N]
// CTA tile 128x128, BK=32, 8 warps (4M x 2N), warp tile 32x64, m16n8k16.
// Double-buffered smem, XOR-swizzled 64B rows (conflict-free LDSM + STS).
// ===========================================================================
#define GBM 128
#define GBN 128
#define GBK 32
#define TILE_B 8192                 // 128 rows x 32 bf16 (64B/row)
#define BUF_B  (4*TILE_B)           // Ah, Al, Wh, Wl
#define GEMM_SMEM_BYTES (2*BUF_B)   // 65536

__device__ __forceinline__ uint32_t smem_u32(const void* p) {
    uint32_t a;
    asm("{ .reg .u64 t; cvta.to.shared.u64 t, %1; cvt.u32.u64 %0, t; }"
        : "=r"(a) : "l"(p));
    return a;
}

// byte offset inside one 128x32-bf16 tile (64B rows, 16B chunk xor swizzle)
__device__ __forceinline__ uint32_t swz(uint32_t row, uint32_t kbyte) {
    uint32_t chunk = ((kbyte >> 4) ^ ((row >> 1) & 3u)) & 3u;
    return row * 64u + chunk * 16u + (kbyte & 15u);
}

__device__ __forceinline__ void ldsm4(uint32_t* r, uint32_t addr) {
    asm volatile("ldmatrix.sync.aligned.m8n8.x4.shared.b16 {%0,%1,%2,%3}, [%4];"
                 : "=r"(r[0]), "=r"(r[1]), "=r"(r[2]), "=r"(r[3]) : "r"(addr));
}

__device__ __forceinline__ void mma16816(float* c, const uint32_t* a,
                                         const uint32_t* b) {
    asm volatile(
        "mma.sync.aligned.m16n8k16.row.col.f32.bf16.bf16.f32 "
        "{%0,%1,%2,%3}, {%4,%5,%6,%7}, {%8,%9}, {%0,%1,%2,%3};"
        : "+f"(c[0]), "+f"(c[1]), "+f"(c[2]), "+f"(c[3])
        : "r"(a[0]), "r"(a[1]), "r"(a[2]), "r"(a[3]), "r"(b[0]), "r"(b[1]));
}

// split float4 -> hi bf16x2 pair + lo bf16x2 pair (each 8 bytes)
__device__ __forceinline__ void split4(float4 v, uint2& hi, uint2& lo) {
    __nv_bfloat162 h0 = __floats2bfloat162_rn(v.x, v.y);
    __nv_bfloat162 h1 = __floats2bfloat162_rn(v.z, v.w);
    float lx = v.x - __bfloat162float(h0.x);
    float ly = v.y - __bfloat162float(h0.y);
    float lz = v.z - __bfloat162float(h1.x);
    float lw = v.w - __bfloat162float(h1.y);
    __nv_bfloat162 l0 = __floats2bfloat162_rn(lx, ly);
    __nv_bfloat162 l1 = __floats2bfloat162_rn(lz, lw);
    hi.x = *(uint32_t*)&h0; hi.y = *(uint32_t*)&h1;
    lo.x = *(uint32_t*)&l0; lo.y = *(uint32_t*)&l1;
}

__device__ __forceinline__ void gemm_mma(const float* __restrict__ A,
                                         const float* __restrict__ W,
                                         const float* __restrict__ bias,
                                         float* __restrict__ C)
{
    extern __shared__ char gsmem[];
    __shared__ float s_bias[GBN];

    const int tid  = threadIdx.x;
    const int lane = tid & 31;
    const int wid  = tid >> 5;
    const int wm   = wid >> 1;          // 0..3 -> m offset wm*32
    const int wn   = wid & 1;           // 0..1 -> n offset wn*64
    const uint32_t sbase = smem_u32(gsmem);

    const int row0 = blockIdx.y * GBM;
    const int col0 = blockIdx.x * GBN;

    if (tid < GBN) s_bias[tid] = bias[col0 + tid];

    // ---- staging geometry: idx = tid + i*256; row = idx>>3, k4 = idx&7 ----
    const int srow = tid >> 3;          // 0..31 (+32 per i)
    const int sk4  = tid & 7;           // float4 index along K (8 per row)
    const float* Ap = A + (size_t)(row0 + srow) * EDIM + sk4 * 4;
    const float* Wp = W + (size_t)(col0 + srow) * EDIM + sk4 * 4;
    uint32_t soff[4];
#pragma unroll
    for (int i = 0; i < 4; i++)
        soff[i] = swz((uint32_t)(srow + i*32), (uint32_t)sk4 * 8u);

    float acc[2][8][4];
#pragma unroll
    for (int mt = 0; mt < 2; mt++)
#pragma unroll
        for (int nt = 0; nt < 8; nt++)
#pragma unroll
            for (int j = 0; j < 4; j++) acc[mt][nt][j] = 0.f;

    // ldmatrix per-lane address pieces
    const uint32_t lrow = (uint32_t)(lane & 15);
    const uint32_t lkb  = (uint32_t)(lane & 16);   // +16B for upper half lanes

    float4 av[4], wv[4];

    // ---- stage chunk 0 ----
#pragma unroll
    for (int i = 0; i < 4; i++) { av[i] = *(const float4*)(Ap + (size_t)i*32*EDIM);
                                  wv[i] = *(const float4*)(Wp + (size_t)i*32*EDIM); }
    {
        char* sb = gsmem;
#pragma unroll
        for (int i = 0; i < 4; i++) {
            uint2 hi, lo;
            split4(av[i], hi, lo);
            *(uint2*)(sb + 0*TILE_B + soff[i]) = hi;
            *(uint2*)(sb + 1*TILE_B + soff[i]) = lo;
            split4(wv[i], hi, lo);
            *(uint2*)(sb + 2*TILE_B + soff[i]) = hi;
            *(uint2*)(sb + 3*TILE_B + soff[i]) = lo;
        }
    }

    const int NCHUNK = EDIM / GBK;      // 32
    for (int c = 0; c < NCHUNK; c++) {
        const bool has_next = (c + 1) < NCHUNK;
        if (has_next) {
            const int k0 = (c + 1) * GBK;
#pragma unroll
            for (int i = 0; i < 4; i++) {
                av[i] = *(const float4*)(Ap + (size_t)i*32*EDIM + k0);
                wv[i] = *(const float4*)(Wp + (size_t)i*32*EDIM + k0);
            }
        }
        __syncthreads();   // buffer c fully staged; prior buffer's mma done

        const uint32_t bb = sbase + (uint32_t)(c & 1) * BUF_B;
#pragma unroll
        for (int k16 = 0; k16 < 2; k16++) {
            const uint32_t kb = (uint32_t)k16 * 32u + lkb;
            uint32_t aH[2][4], aL[2][4], bH[8][2], bL[8][2];
#pragma unroll
            for (int mt = 0; mt < 2; mt++) {
                uint32_t r = (uint32_t)(wm*32 + mt*16) + lrow;
                ldsm4(aH[mt], bb + 0*TILE_B + swz(r, kb));
                ldsm4(aL[mt], bb + 1*TILE_B + swz(r, kb));
            }
#pragma unroll
            for (int g = 0; g < 4; g++) {
                uint32_t r = (uint32_t)(wn*64 + g*16) + lrow;
                uint32_t t[4];
                ldsm4(t, bb + 2*TILE_B + swz(r, kb));
                bH[g*2][0]   = t[0]; bH[g*2][1]   = t[2];
                bH[g*2+1][0] = t[1]; bH[g*2+1][1] = t[3];
                ldsm4(t, bb + 3*TILE_B + swz(r, kb));
                bL[g*2][0]   = t[0]; bL[g*2][1]   = t[2];
                bL[g*2+1][0] = t[1]; bL[g*2+1][1] = t[3];
            }
#pragma unroll
            for (int mt = 0; mt < 2; mt++)
#pragma unroll
                for (int nt = 0; nt < 8; nt++) {
                    mma16816(acc[mt][nt], aH[mt], bH[nt]);
                    mma16816(acc[mt][nt], aH[mt], bL[nt]);
                    mma16816(acc[mt][nt], aL[mt], bH[nt]);
                }
        }

        if (has_next) {
            char* sb = gsmem + ((c + 1) & 1) * BUF_B;
#pragma unroll
            for (int i = 0; i < 4; i++) {
                uint2 hi, lo;
                split4(av[i], hi, lo);
                *(uint2*)(sb + 0*TILE_B + soff[i]) = hi;
                *(uint2*)(sb + 1*TILE_B + soff[i]) = lo;
                split4(wv[i], hi, lo);
                *(uint2*)(sb + 2*TILE_B + soff[i]) = hi;
                *(uint2*)(sb + 3*TILE_B + soff[i]) = lo;
            }
        }
    }

    // ---- epilogue: acc -> C (+bias) ----
    const int erow = lane >> 2;
    const int ecol = (lane & 3) * 2;
#pragma unroll
    for (int mt = 0; mt < 2; mt++) {
        const int rbase = row0 + wm*32 + mt*16 + erow;
#pragma unroll
        for (int nt = 0; nt < 8; nt++) {
            const int cb = wn*64 + nt*8 + ecol;
            const float b0 = s_bias[cb], b1 = s_bias[cb+1];
            float2 v0 = {acc[mt][nt][0] + b0, acc[mt][nt][1] + b1};
            float2 v1 = {acc[mt][nt][2] + b0, acc[mt][nt][3] + b1};
            *(float2*)&C[(size_t)rbase * EDIM + col0 + cb]       = v0;
            *(float2*)&C[(size_t)(rbase + 8) * EDIM + col0 + cb] = v1;
        }
    }
}

__global__ void __launch_bounds__(256, 1)
proj_qkv_kernel(const float* __restrict__ q, const float* __restrict__ k,
                const float* __restrict__ v,
                const float* __restrict__ Wq, const float* __restrict__ bq,
                const float* __restrict__ Wk, const float* __restrict__ bk,
                const float* __restrict__ Wv, const float* __restrict__ bv)
{
    const float *A, *W, *b; float* C;
    if (blockIdx.z == 0)      { A = q; W = Wq; b = bq; C = g_Q; }
    else if (blockIdx.z == 1) { A = k; W = Wk; b = bk; C = g_K; }
    else                      { A = v; W = Wv; b = bv; C = g_V; }
    gemm_mma(A, W, b, C);
}

__global__ void __launch_bounds__(256, 1)
out_proj_kernel(const float* __restrict__ Wo, const float* __restrict__ bo,
                float* __restrict__ out)
{
    gemm_mma(g_A, Wo, bo, out);
}

// ---------------------------------------------------------------------------
// Sliding-window attention, flash-style (unchanged from R1).
// ---------------------------------------------------------------------------
#define BQ   128
#define BKC  128
#define QSTR 132
#define VSTR 68
#define PSTR 132

#define SQT_SZ (HDIM*QSTR)
#define SKT_SZ (HDIM*QSTR)
#define SV_SZ  (BKC*VSTR)
#define SP_SZ  (BQ*PSTR)
#define ATTN_SMEM_FLOATS (SQT_SZ + SKT_SZ + SV_SZ + SP_SZ)
#define ATTN_SMEM_BYTES  (ATTN_SMEM_FLOATS * 4)

__global__ void __launch_bounds__(256)
attn_kernel()
{
    extern __shared__ float smem[];
    float* sQt = smem;
    float* sKt = sQt + SQT_SZ;
    float* sV  = sKt + SKT_SZ;
    float* sP  = sV  + SV_SZ;

    const int tid = threadIdx.x;
    const int tx  = tid & 15;
    const int ty  = tid >> 4;
    const int qb  = blockIdx.x;
    const int h   = blockIdx.y;
    const int b   = blockIdx.z;
    const int q0  = qb * BQ;

    const float* Qb = g_Q + (size_t)b*SEQ*EDIM + (size_t)h*HDIM;
    const float* Kb = g_K + (size_t)b*SEQ*EDIM + (size_t)h*HDIM;
    const float* Vb = g_V + (size_t)b*SEQ*EDIM + (size_t)h*HDIM;
    float*       Ob = g_A + (size_t)b*SEQ*EDIM + (size_t)h*HDIM;

#pragma unroll
    for (int it = 0; it < 8; it++) {
        int idx = tid + it*256;
        int r  = idx >> 4;
        int d4 = (idx & 15) << 2;
        float4 qv = *(const float4*)(Qb + (size_t)(q0 + r)*EDIM + d4);
        sQt[(d4+0)*QSTR + r] = qv.x;
        sQt[(d4+1)*QSTR + r] = qv.y;
        sQt[(d4+2)*QSTR + r] = qv.z;
        sQt[(d4+3)*QSTR + r] = qv.w;
    }

    const int i0 = ty * 8;
    const int d0 = tx * 4;
    float m_i[8], l_i[8], o[8][4];
#pragma unroll
    for (int i = 0; i < 8; i++) {
        m_i[i] = -1e30f; l_i[i] = 0.f;
        o[i][0]=o[i][1]=o[i][2]=o[i][3]=0.f;
    }

    const int nkb = SEQ / BKC;
    for (int kb = qb - 1; kb <= qb + 1; kb++) {
        if (kb < 0 || kb >= nkb) continue;
        const int j0 = kb * BKC;

        __syncthreads();
#pragma unroll
        for (int it = 0; it < 8; it++) {
            int idx = tid + it*256;
            int r  = idx >> 4;
            int d4 = (idx & 15) << 2;
            float4 kv = *(const float4*)(Kb + (size_t)(j0 + r)*EDIM + d4);
            sKt[(d4+0)*QSTR + r] = kv.x;
            sKt[(d4+1)*QSTR + r] = kv.y;
            sKt[(d4+2)*QSTR + r] = kv.z;
            sKt[(d4+3)*QSTR + r] = kv.w;
            float4 vv = *(const float4*)(Vb + (size_t)(j0 + r)*EDIM + d4);
            *(float4*)&sV[r*VSTR + d4] = vv;
        }
        __syncthreads();

        float s[8][8];
#pragma unroll
        for (int i = 0; i < 8; i++)
#pragma unroll
            for (int j = 0; j < 8; j++) s[i][j] = 0.f;

#pragma unroll 4
        for (int d = 0; d < HDIM; d++) {
            float4 a0 = *(const float4*)&sQt[d*QSTR + i0];
            float4 a1 = *(const float4*)&sQt[d*QSTR + i0 + 4];
            float4 b0 = *(const float4*)&sKt[d*QSTR + tx*8];
            float4 b1 = *(const float4*)&sKt[d*QSTR + tx*8 + 4];
            float a[8] = {a0.x,a0.y,a0.z,a0.w,a1.x,a1.y,a1.z,a1.w};
            float bb[8] = {b0.x,b0.y,b0.z,b0.w,b1.x,b1.y,b1.z,b1.w};
#pragma unroll
            for (int i = 0; i < 8; i++)
#pragma unroll
                for (int j = 0; j < 8; j++)
                    s[i][j] = fmaf(a[i], bb[j], s[i][j]);
        }

#pragma unroll
        for (int i = 0; i < 8; i++) {
            int gi = q0 + i0 + i;
#pragma unroll
            for (int j = 0; j < 8; j++) {
                int gj = j0 + tx*8 + j;
                int dd = gi - gj; dd = dd < 0 ? -dd : dd;
                s[i][j] = (dd > WIN) ? -1e30f : s[i][j] * 0.125f;
            }
        }

#pragma unroll
        for (int i = 0; i < 8; i++) {
            float rm = s[i][0];
#pragma unroll
            for (int j = 1; j < 8; j++) rm = fmaxf(rm, s[i][j]);
#pragma unroll
            for (int off = 8; off >= 1; off >>= 1)
                rm = fmaxf(rm, __shfl_xor_sync(0xffffffffu, rm, off));
            float mnew = fmaxf(m_i[i], rm);
            float corr = __expf(m_i[i] - mnew);
            float rs = 0.f;
#pragma unroll
            for (int j = 0; j < 8; j++) {
                float p = __expf(s[i][j] - mnew);
                s[i][j] = p; rs += p;
            }
#pragma unroll
            for (int off = 8; off >= 1; off >>= 1)
                rs += __shfl_xor_sync(0xffffffffu, rs, off);
            l_i[i] = l_i[i] * corr + rs;
            m_i[i] = mnew;
            o[i][0] *= corr; o[i][1] *= corr; o[i][2] *= corr; o[i][3] *= corr;
        }

#pragma unroll
        for (int i = 0; i < 8; i++) {
            float4 p0 = {s[i][0], s[i][1], s[i][2], s[i][3]};
            float4 p1 = {s[i][4], s[i][5], s[i][6], s[i][7]};
            *(float4*)&sP[(i0+i)*PSTR + tx*8]     = p0;
            *(float4*)&sP[(i0+i)*PSTR + tx*8 + 4] = p1;
        }
        __syncthreads();

#pragma unroll 2
        for (int j = 0; j < BKC; j++) {
            float4 vv = *(const float4*)&sV[j*VSTR + d0];
#pragma unroll
            for (int i = 0; i < 8; i++) {
                float p = sP[(i0+i)*PSTR + j];
                o[i][0] = fmaf(p, vv.x, o[i][0]);
                o[i][1] = fmaf(p, vv.y, o[i][1]);
                o[i][2] = fmaf(p, vv.z, o[i][2]);
                o[i][3] = fmaf(p, vv.w, o[i][3]);
            }
        }
    }

#pragma unroll
    for (int i = 0; i < 8; i++) {
        float inv = 1.0f / l_i[i];
        float4 res = {o[i][0]*inv, o[i][1]*inv, o[i][2]*inv, o[i][3]*inv};
        *(float4*)(Ob + (size_t)(q0 + i0 + i)*EDIM + d0) = res;
    }
}

// ---------------------------------------------------------------------------
extern "C" void kernel_launch(void* const* d_in, const int* in_sizes, int n_in,
                              void* d_out, int out_size)
{
    const float* q  = (const float*)d_in[0];
    const float* k  = (const float*)d_in[1];
    const float* v  = (const float*)d_in[2];
    const float* Wq = (const float*)d_in[3];
    const float* bq = (const float*)d_in[4];
    const float* Wk = (const float*)d_in[5];
    const float* bk = (const float*)d_in[6];
    const float* Wv = (const float*)d_in[7];
    const float* bv = (const float*)d_in[8];
    const float* Wo = (const float*)d_in[9];
    const float* bo = (const float*)d_in[10];
    float* out = (float*)d_out;

    cudaFuncSetAttribute(attn_kernel,
                         cudaFuncAttributeMaxDynamicSharedMemorySize,
                         ATTN_SMEM_BYTES);
    cudaFuncSetAttribute(proj_qkv_kernel,
                         cudaFuncAttributeMaxDynamicSharedMemorySize,
                         GEMM_SMEM_BYTES);
    cudaFuncSetAttribute(out_proj_kernel,
                         cudaFuncAttributeMaxDynamicSharedMemorySize,
                         GEMM_SMEM_BYTES);

    dim3 gProj(EDIM/GBN, MROWS/GBM, 3);
    proj_qkv_kernel<<<gProj, 256, GEMM_SMEM_BYTES>>>(q, k, v, Wq, bq, Wk, bk, Wv, bv);

    dim3 gAttn(SEQ/BQ, NHEADS, BATCH);
    attn_kernel<<<gAttn, 256, ATTN_SMEM_BYTES>>>();

    dim3 gOut(EDIM/GBN, MROWS/GBM, 1);
    out_proj_kernel<<<gOut, 256, GEMM_SMEM_BYTES>>>(Wo, bo, out);
}

// round 4
// speedup vs baseline: 2.5310x; 1.2874x over previous
#include <cuda_runtime.h>
#include <cuda_bf16.h>
#include <cstdint>

#define EDIM   1024
#define BATCH  2
#define SEQ    2048
#define NHEADS 16
#define HDIM   64
#define WIN    128
#define MROWS  (BATCH*SEQ)

// Scratch (allocation-free rule: __device__ globals)
__device__ float g_Q[MROWS*EDIM];
__device__ float g_K[MROWS*EDIM];
__device__ float g_V[MROWS*EDIM];
__device__ float g_A[MROWS*EDIM];

// ===========================================================================
// Shared helpers
// ===========================================================================
__device__ __forceinline__ uint32_t smem_u32(const void* p) {
    uint32_t a;
    asm("{ .reg .u64 t; cvta.to.shared.u64 t, %1; cvt.u32.u64 %0, t; }"
        : "=r"(a) : "l"(p));
    return a;
}

__device__ __forceinline__ void ldsm4(uint32_t* r, uint32_t addr) {
    asm volatile("ldmatrix.sync.aligned.m8n8.x4.shared.b16 {%0,%1,%2,%3}, [%4];"
                 : "=r"(r[0]), "=r"(r[1]), "=r"(r[2]), "=r"(r[3]) : "r"(addr));
}
__device__ __forceinline__ void ldsm4t(uint32_t* r, uint32_t addr) {
    asm volatile("ldmatrix.sync.aligned.m8n8.x4.trans.shared.b16 {%0,%1,%2,%3}, [%4];"
                 : "=r"(r[0]), "=r"(r[1]), "=r"(r[2]), "=r"(r[3]) : "r"(addr));
}

__device__ __forceinline__ void mma16816(float* c, const uint32_t* a,
                                         const uint32_t* b) {
    asm volatile(
        "mma.sync.aligned.m16n8k16.row.col.f32.bf16.bf16.f32 "
        "{%0,%1,%2,%3}, {%4,%5,%6,%7}, {%8,%9}, {%0,%1,%2,%3};"
        : "+f"(c[0]), "+f"(c[1]), "+f"(c[2]), "+f"(c[3])
        : "r"(a[0]), "r"(a[1]), "r"(a[2]), "r"(a[3]), "r"(b[0]), "r"(b[1]));
}

// split float4 -> hi bf16x2 pair + lo bf16x2 pair (each 8 bytes)
__device__ __forceinline__ void split4(float4 v, uint2& hi, uint2& lo) {
    __nv_bfloat162 h0 = __floats2bfloat162_rn(v.x, v.y);
    __nv_bfloat162 h1 = __floats2bfloat162_rn(v.z, v.w);
    float lx = v.x - __bfloat162float(h0.x);
    float ly = v.y - __bfloat162float(h0.y);
    float lz = v.z - __bfloat162float(h1.x);
    float lw = v.w - __bfloat162float(h1.y);
    __nv_bfloat162 l0 = __floats2bfloat162_rn(lx, ly);
    __nv_bfloat162 l1 = __floats2bfloat162_rn(lz, lw);
    hi.x = *(uint32_t*)&h0; hi.y = *(uint32_t*)&h1;
    lo.x = *(uint32_t*)&l0; lo.y = *(uint32_t*)&l1;
}

// ===========================================================================
// bf16 mma.sync GEMM, 3-product compensated split (unchanged from R3)
// ===========================================================================
#define GBM 128
#define GBN 128
#define GBK 32
#define TILE_B 8192
#define BUF_B  (4*TILE_B)
#define GEMM_SMEM_BYTES (2*BUF_B)

__device__ __forceinline__ uint32_t swz(uint32_t row, uint32_t kbyte) {
    uint32_t chunk = ((kbyte >> 4) ^ ((row >> 1) & 3u)) & 3u;
    return row * 64u + chunk * 16u + (kbyte & 15u);
}

__device__ __forceinline__ void gemm_mma(const float* __restrict__ A,
                                         const float* __restrict__ W,
                                         const float* __restrict__ bias,
                                         float* __restrict__ C)
{
    extern __shared__ char gsmem[];
    __shared__ float s_bias[GBN];

    const int tid  = threadIdx.x;
    const int lane = tid & 31;
    const int wid  = tid >> 5;
    const int wm   = wid >> 1;
    const int wn   = wid & 1;
    const uint32_t sbase = smem_u32(gsmem);

    const int row0 = blockIdx.y * GBM;
    const int col0 = blockIdx.x * GBN;

    if (tid < GBN) s_bias[tid] = bias[col0 + tid];

    const int srow = tid >> 3;
    const int sk4  = tid & 7;
    const float* Ap = A + (size_t)(row0 + srow) * EDIM + sk4 * 4;
    const float* Wp = W + (size_t)(col0 + srow) * EDIM + sk4 * 4;
    uint32_t soff[4];
#pragma unroll
    for (int i = 0; i < 4; i++)
        soff[i] = swz((uint32_t)(srow + i*32), (uint32_t)sk4 * 8u);

    float acc[2][8][4];
#pragma unroll
    for (int mt = 0; mt < 2; mt++)
#pragma unroll
        for (int nt = 0; nt < 8; nt++)
#pragma unroll
            for (int j = 0; j < 4; j++) acc[mt][nt][j] = 0.f;

    const uint32_t lrow = (uint32_t)(lane & 15);
    const uint32_t lkb  = (uint32_t)(lane & 16);

    float4 av[4], wv[4];
#pragma unroll
    for (int i = 0; i < 4; i++) { av[i] = *(const float4*)(Ap + (size_t)i*32*EDIM);
                                  wv[i] = *(const float4*)(Wp + (size_t)i*32*EDIM); }
    {
        char* sb = gsmem;
#pragma unroll
        for (int i = 0; i < 4; i++) {
            uint2 hi, lo;
            split4(av[i], hi, lo);
            *(uint2*)(sb + 0*TILE_B + soff[i]) = hi;
            *(uint2*)(sb + 1*TILE_B + soff[i]) = lo;
            split4(wv[i], hi, lo);
            *(uint2*)(sb + 2*TILE_B + soff[i]) = hi;
            *(uint2*)(sb + 3*TILE_B + soff[i]) = lo;
        }
    }

    const int NCHUNK = EDIM / GBK;
    for (int c = 0; c < NCHUNK; c++) {
        const bool has_next = (c + 1) < NCHUNK;
        if (has_next) {
            const int k0 = (c + 1) * GBK;
#pragma unroll
            for (int i = 0; i < 4; i++) {
                av[i] = *(const float4*)(Ap + (size_t)i*32*EDIM + k0);
                wv[i] = *(const float4*)(Wp + (size_t)i*32*EDIM + k0);
            }
        }
        __syncthreads();

        const uint32_t bb = sbase + (uint32_t)(c & 1) * BUF_B;
#pragma unroll
        for (int k16 = 0; k16 < 2; k16++) {
            const uint32_t kb = (uint32_t)k16 * 32u + lkb;
            uint32_t aH[2][4], aL[2][4], bH[8][2], bL[8][2];
#pragma unroll
            for (int mt = 0; mt < 2; mt++) {
                uint32_t r = (uint32_t)(wm*32 + mt*16) + lrow;
                ldsm4(aH[mt], bb + 0*TILE_B + swz(r, kb));
                ldsm4(aL[mt], bb + 1*TILE_B + swz(r, kb));
            }
#pragma unroll
            for (int g = 0; g < 4; g++) {
                uint32_t r = (uint32_t)(wn*64 + g*16) + lrow;
                uint32_t t[4];
                ldsm4(t, bb + 2*TILE_B + swz(r, kb));
                bH[g*2][0]   = t[0]; bH[g*2][1]   = t[2];
                bH[g*2+1][0] = t[1]; bH[g*2+1][1] = t[3];
                ldsm4(t, bb + 3*TILE_B + swz(r, kb));
                bL[g*2][0]   = t[0]; bL[g*2][1]   = t[2];
                bL[g*2+1][0] = t[1]; bL[g*2+1][1] = t[3];
            }
#pragma unroll
            for (int mt = 0; mt < 2; mt++)
#pragma unroll
                for (int nt = 0; nt < 8; nt++) {
                    mma16816(acc[mt][nt], aH[mt], bH[nt]);
                    mma16816(acc[mt][nt], aH[mt], bL[nt]);
                    mma16816(acc[mt][nt], aL[mt], bH[nt]);
                }
        }

        if (has_next) {
            char* sb = gsmem + ((c + 1) & 1) * BUF_B;
#pragma unroll
            for (int i = 0; i < 4; i++) {
                uint2 hi, lo;
                split4(av[i], hi, lo);
                *(uint2*)(sb + 0*TILE_B + soff[i]) = hi;
                *(uint2*)(sb + 1*TILE_B + soff[i]) = lo;
                split4(wv[i], hi, lo);
                *(uint2*)(sb + 2*TILE_B + soff[i]) = hi;
                *(uint2*)(sb + 3*TILE_B + soff[i]) = lo;
            }
        }
    }

    const int erow = lane >> 2;
    const int ecol = (lane & 3) * 2;
#pragma unroll
    for (int mt = 0; mt < 2; mt++) {
        const int rbase = row0 + wm*32 + mt*16 + erow;
#pragma unroll
        for (int nt = 0; nt < 8; nt++) {
            const int cb = wn*64 + nt*8 + ecol;
            const float b0 = s_bias[cb], b1 = s_bias[cb+1];
            float2 v0 = {acc[mt][nt][0] + b0, acc[mt][nt][1] + b1};
            float2 v1 = {acc[mt][nt][2] + b0, acc[mt][nt][3] + b1};
            *(float2*)&C[(size_t)rbase * EDIM + col0 + cb]       = v0;
            *(float2*)&C[(size_t)(rbase + 8) * EDIM + col0 + cb] = v1;
        }
    }
}

__global__ void __launch_bounds__(256, 1)
proj_qkv_kernel(const float* __restrict__ q, const float* __restrict__ k,
                const float* __restrict__ v,
                const float* __restrict__ Wq, const float* __restrict__ bq,
                const float* __restrict__ Wk, const float* __restrict__ bk,
                const float* __restrict__ Wv, const float* __restrict__ bv)
{
    const float *A, *W, *b; float* C;
    if (blockIdx.z == 0)      { A = q; W = Wq; b = bq; C = g_Q; }
    else if (blockIdx.z == 1) { A = k; W = Wk; b = bk; C = g_K; }
    else                      { A = v; W = Wv; b = bv; C = g_V; }
    gemm_mma(A, W, b, C);
}

__global__ void __launch_bounds__(256, 1)
out_proj_kernel(const float* __restrict__ Wo, const float* __restrict__ bo,
                float* __restrict__ out)
{
    gemm_mma(g_A, Wo, bo, out);
}

// ===========================================================================
// Tensor-core sliding-window attention (FA2-style, compensated bf16 split).
// One CTA per (128-query block, head, batch). 8 warps, each 16 q rows.
// smem tiles: 128 rows x 64 bf16 (128B rows), xor-swizzled, hi+lo per matrix.
// ===========================================================================
#define ATT_TILE 16384   // 128*64*2 bytes
#define ATT_SMEM_BYTES (6*ATT_TILE)   // Qh Ql Kh Kl Vh Vl = 96KB

// 128-byte-row swizzle (8 chunks of 16B, xor with row%8)
__device__ __forceinline__ uint32_t swzA(uint32_t row, uint32_t cb) {
    return row * 128u + ((((cb >> 4) ^ (row & 7u)) & 7u) << 4) + (cb & 15u);
}

// stage a 128x64 fp32 tile (row stride EDIM) into bf16 hi/lo swizzled smem
__device__ __forceinline__ void stage_tile(const float* __restrict__ src,
                                           char* dstH, char* dstL, int tid)
{
#pragma unroll
    for (int it = 0; it < 8; it++) {
        int idx = tid + it * 256;
        int row = idx >> 4;
        int d4  = (idx & 15) << 2;
        float4 v = *(const float4*)(src + (size_t)row * EDIM + d4);
        uint2 hi, lo;
        split4(v, hi, lo);
        uint32_t off = swzA((uint32_t)row, (uint32_t)d4 * 2u);
        *(uint2*)(dstH + off) = hi;
        *(uint2*)(dstL + off) = lo;
    }
}

__global__ void __launch_bounds__(256, 1)
attn_kernel()
{
    extern __shared__ char asmem[];
    char* sQh = asmem;
    char* sQl = asmem + 1*ATT_TILE;
    char* sKh = asmem + 2*ATT_TILE;
    char* sKl = asmem + 3*ATT_TILE;
    char* sVh = asmem + 4*ATT_TILE;
    char* sVl = asmem + 5*ATT_TILE;
    const uint32_t uQh = smem_u32(sQh), uQl = smem_u32(sQl);
    const uint32_t uKh = smem_u32(sKh), uKl = smem_u32(sKl);
    const uint32_t uVh = smem_u32(sVh), uVl = smem_u32(sVl);

    const int tid  = threadIdx.x;
    const int lane = tid & 31;
    const int wid  = tid >> 5;
    const int qb   = blockIdx.x;
    const int h    = blockIdx.y;
    const int b    = blockIdx.z;
    const int q0   = qb * 128;
    const int qw   = wid * 16;          // warp's q-row base within block

    const float* Qb = g_Q + (size_t)b*SEQ*EDIM + (size_t)h*HDIM;
    const float* Kb = g_K + (size_t)b*SEQ*EDIM + (size_t)h*HDIM;
    const float* Vb = g_V + (size_t)b*SEQ*EDIM + (size_t)h*HDIM;
    float*       Ob = g_A + (size_t)b*SEQ*EDIM + (size_t)h*HDIM;

    stage_tile(Qb + (size_t)q0*EDIM, sQh, sQl, tid);

    // per-thread row ids (2 rows)
    const int r0g = q0 + qw + (lane >> 2);      // global q row 0
    // softmax state
    float m0 = -1e30f, m1 = -1e30f, l0 = 0.f, l1 = 0.f;
    float oacc[8][4];
#pragma unroll
    for (int nt = 0; nt < 8; nt++)
#pragma unroll
        for (int j = 0; j < 4; j++) oacc[nt][j] = 0.f;

    // ldmatrix lane-address components
    const uint32_t aRow = (uint32_t)(qw + (lane & 15));            // A (Q)
    const uint32_t aKb  = (uint32_t)(lane & 16);
    const uint32_t bRowOff = (uint32_t)((lane & 7) + ((lane & 16) ? 8 : 0));  // B (K)
    const uint32_t bKb  = (uint32_t)((lane & 8) ? 16 : 0);
    const uint32_t vRowOff = (uint32_t)((lane & 7) + ((lane & 8) ? 8 : 0));   // B (V, trans)
    const uint32_t vKb  = (uint32_t)((lane & 16) ? 16 : 0);

    const int nkb = SEQ / 128;
    for (int kb = qb - 1; kb <= qb + 1; kb++) {
        if (kb < 0 || kb >= nkb) continue;
        const int j0 = kb * 128;
        const int rel = (kb - qb) * 128;

        __syncthreads();   // previous chunk's smem reads done
        stage_tile(Kb + (size_t)j0*EDIM, sKh, sKl, tid);
        stage_tile(Vb + (size_t)j0*EDIM, sVh, sVl, tid);
        __syncthreads();

        // in-band n16-group range for this warp
        int lo = qw - WIN - rel;          if (lo < 0) lo = 0;
        int hi = qw + 15 + WIN + 1 - rel; if (hi > 128) hi = 128;
        const int t16lo = lo >> 4;
        const int t16hi = (hi + 15) >> 4;

        // ---- S = Q K^T ----
        float sacc[16][4];
#pragma unroll
        for (int nt = 0; nt < 16; nt++)
#pragma unroll
            for (int j = 0; j < 4; j++) sacc[nt][j] = 0.f;

#pragma unroll
        for (int k16 = 0; k16 < 4; k16++) {
            const uint32_t kcb = (uint32_t)k16 * 32u + aKb;
            uint32_t aH[4], aL[4];
            ldsm4(aH, uQh + swzA(aRow, kcb));
            ldsm4(aL, uQl + swzA(aRow, kcb));
            const uint32_t kcbB = (uint32_t)k16 * 32u + bKb;
#pragma unroll
            for (int g = 0; g < 8; g++) {
                if (g < t16lo || g >= t16hi) continue;
                const uint32_t rr = (uint32_t)(g * 16) + bRowOff;
                uint32_t tH[4], tL[4];
                ldsm4(tH, uKh + swzA(rr, kcbB));
                ldsm4(tL, uKl + swzA(rr, kcbB));
                uint32_t b0h[2] = {tH[0], tH[1]}, b1h[2] = {tH[2], tH[3]};
                uint32_t b0l[2] = {tL[0], tL[1]}, b1l[2] = {tL[2], tL[3]};
                mma16816(sacc[2*g],   aH, b0h);
                mma16816(sacc[2*g],   aH, b0l);
                mma16816(sacc[2*g],   aL, b0h);
                mma16816(sacc[2*g+1], aH, b1h);
                mma16816(sacc[2*g+1], aH, b1l);
                mma16816(sacc[2*g+1], aL, b1h);
            }
        }

        // ---- scale + mask + online softmax ----
        const int cquad = (lane & 3) << 1;
        float mx0 = -1e30f, mx1 = -1e30f;
#pragma unroll
        for (int nt = 0; nt < 16; nt++) {
            const int gj = j0 + nt*8 + cquad;
            int d00 = r0g - gj;     d00 = d00 < 0 ? -d00 : d00;
            int d01 = r0g - gj - 1; d01 = d01 < 0 ? -d01 : d01;
            int d10 = r0g + 8 - gj;     d10 = d10 < 0 ? -d10 : d10;
            int d11 = r0g + 8 - gj - 1; d11 = d11 < 0 ? -d11 : d11;
            sacc[nt][0] = (d00 > WIN) ? -1e30f : sacc[nt][0] * 0.125f;
            sacc[nt][1] = (d01 > WIN) ? -1e30f : sacc[nt][1] * 0.125f;
            sacc[nt][2] = (d10 > WIN) ? -1e30f : sacc[nt][2] * 0.125f;
            sacc[nt][3] = (d11 > WIN) ? -1e30f : sacc[nt][3] * 0.125f;
            mx0 = fmaxf(mx0, fmaxf(sacc[nt][0], sacc[nt][1]));
            mx1 = fmaxf(mx1, fmaxf(sacc[nt][2], sacc[nt][3]));
        }
        mx0 = fmaxf(mx0, __shfl_xor_sync(0xffffffffu, mx0, 1));
        mx0 = fmaxf(mx0, __shfl_xor_sync(0xffffffffu, mx0, 2));
        mx1 = fmaxf(mx1, __shfl_xor_sync(0xffffffffu, mx1, 1));
        mx1 = fmaxf(mx1, __shfl_xor_sync(0xffffffffu, mx1, 2));

        const float mn0 = fmaxf(m0, mx0);
        const float mn1 = fmaxf(m1, mx1);
        const float cr0 = __expf(m0 - mn0);
        const float cr1 = __expf(m1 - mn1);
        float rs0 = 0.f, rs1 = 0.f;
#pragma unroll
        for (int nt = 0; nt < 16; nt++) {
            float p0 = __expf(sacc[nt][0] - mn0);
            float p1 = __expf(sacc[nt][1] - mn0);
            float p2 = __expf(sacc[nt][2] - mn1);
            float p3 = __expf(sacc[nt][3] - mn1);
            sacc[nt][0] = p0; sacc[nt][1] = p1;
            sacc[nt][2] = p2; sacc[nt][3] = p3;
            rs0 += p0 + p1; rs1 += p2 + p3;
        }
        rs0 += __shfl_xor_sync(0xffffffffu, rs0, 1);
        rs0 += __shfl_xor_sync(0xffffffffu, rs0, 2);
        rs1 += __shfl_xor_sync(0xffffffffu, rs1, 1);
        rs1 += __shfl_xor_sync(0xffffffffu, rs1, 2);
        l0 = l0 * cr0 + rs0;  m0 = mn0;
        l1 = l1 * cr1 + rs1;  m1 = mn1;
#pragma unroll
        for (int nt = 0; nt < 8; nt++) {
            oacc[nt][0] *= cr0; oacc[nt][1] *= cr0;
            oacc[nt][2] *= cr1; oacc[nt][3] *= cr1;
        }

        // ---- O += P V ----
#pragma unroll
        for (int kk = 0; kk < 8; kk++) {
            if (kk < t16lo || kk >= t16hi) continue;
            // pack P frags from accum tiles 2kk, 2kk+1
            uint32_t ph[4], pl[4];
            {
                const float* p0 = sacc[2*kk];
                const float* p1 = sacc[2*kk + 1];
                __nv_bfloat162 h;
                h = __floats2bfloat162_rn(p0[0], p0[1]); ph[0] = *(uint32_t*)&h;
                float l0a = p0[0]-__bfloat162float(h.x), l0b = p0[1]-__bfloat162float(h.y);
                h = __floats2bfloat162_rn(p0[2], p0[3]); ph[1] = *(uint32_t*)&h;
                float l1a = p0[2]-__bfloat162float(h.x), l1b = p0[3]-__bfloat162float(h.y);
                h = __floats2bfloat162_rn(p1[0], p1[1]); ph[2] = *(uint32_t*)&h;
                float l2a = p1[0]-__bfloat162float(h.x), l2b = p1[1]-__bfloat162float(h.y);
                h = __floats2bfloat162_rn(p1[2], p1[3]); ph[3] = *(uint32_t*)&h;
                float l3a = p1[2]-__bfloat162float(h.x), l3b = p1[3]-__bfloat162float(h.y);
                h = __floats2bfloat162_rn(l0a, l0b); pl[0] = *(uint32_t*)&h;
                h = __floats2bfloat162_rn(l1a, l1b); pl[1] = *(uint32_t*)&h;
                h = __floats2bfloat162_rn(l2a, l2b); pl[2] = *(uint32_t*)&h;
                h = __floats2bfloat162_rn(l3a, l3b); pl[3] = *(uint32_t*)&h;
            }
            const uint32_t vRow = (uint32_t)(kk * 16) + vRowOff;
#pragma unroll
            for (int g2 = 0; g2 < 4; g2++) {
                const uint32_t dcb = (uint32_t)g2 * 32u + vKb;
                uint32_t tH[4], tL[4];
                ldsm4t(tH, uVh + swzA(vRow, dcb));
                ldsm4t(tL, uVl + swzA(vRow, dcb));
                uint32_t b0h[2] = {tH[0], tH[1]}, b1h[2] = {tH[2], tH[3]};
                uint32_t b0l[2] = {tL[0], tL[1]}, b1l[2] = {tL[2], tL[3]};
                mma16816(oacc[2*g2],   ph, b0h);
                mma16816(oacc[2*g2],   ph, b0l);
                mma16816(oacc[2*g2],   pl, b0h);
                mma16816(oacc[2*g2+1], ph, b1h);
                mma16816(oacc[2*g2+1], ph, b1l);
                mma16816(oacc[2*g2+1], pl, b1h);
            }
        }
    }

    // ---- normalize + store ----
    const float inv0 = 1.0f / l0;
    const float inv1 = 1.0f / l1;
    const int dc = (lane & 3) << 1;
#pragma unroll
    for (int nt = 0; nt < 8; nt++) {
        const int dcol = nt*8 + dc;
        float2 v0 = {oacc[nt][0]*inv0, oacc[nt][1]*inv0};
        float2 v1 = {oacc[nt][2]*inv1, oacc[nt][3]*inv1};
        *(float2*)(Ob + (size_t)r0g*EDIM + dcol)       = v0;
        *(float2*)(Ob + (size_t)(r0g+8)*EDIM + dcol)   = v1;
    }
}

// ---------------------------------------------------------------------------
extern "C" void kernel_launch(void* const* d_in, const int* in_sizes, int n_in,
                              void* d_out, int out_size)
{
    const float* q  = (const float*)d_in[0];
    const float* k  = (const float*)d_in[1];
    const float* v  = (const float*)d_in[2];
    const float* Wq = (const float*)d_in[3];
    const float* bq = (const float*)d_in[4];
    const float* Wk = (const float*)d_in[5];
    const float* bk = (const float*)d_in[6];
    const float* Wv = (const float*)d_in[7];
    const float* bv = (const float*)d_in[8];
    const float* Wo = (const float*)d_in[9];
    const float* bo = (const float*)d_in[10];
    float* out = (float*)d_out;

    cudaFuncSetAttribute(attn_kernel,
                         cudaFuncAttributeMaxDynamicSharedMemorySize,
                         ATT_SMEM_BYTES);
    cudaFuncSetAttribute(proj_qkv_kernel,
                         cudaFuncAttributeMaxDynamicSharedMemorySize,
                         GEMM_SMEM_BYTES);
    cudaFuncSetAttribute(out_proj_kernel,
                         cudaFuncAttributeMaxDynamicSharedMemorySize,
                         GEMM_SMEM_BYTES);

    dim3 gProj(EDIM/GBN, MROWS/GBM, 3);
    proj_qkv_kernel<<<gProj, 256, GEMM_SMEM_BYTES>>>(q, k, v, Wq, bq, Wk, bk, Wv, bv);

    dim3 gAttn(SEQ/128, NHEADS, BATCH);
    attn_kernel<<<gAttn, 256, ATT_SMEM_BYTES>>>();

    dim3 gOut(EDIM/GBN, MROWS/GBM, 1);
    out_proj_kernel<<<gOut, 256, GEMM_SMEM_BYTES>>>(Wo, bo, out);
}